// round 5
// baseline (speedup 1.0000x reference)
#include <cuda_runtime.h>
#include <cstdint>
#include <cstddef>

// ============================================================================
// Problem constants
// ============================================================================
static constexpr int N_TOK = 32768;
static constexpr int DIN   = 2048;
static constexpr int DOUT  = 2048;
static constexpr int LNUM  = 8;
static constexpr int RNK   = 16;
static constexpr int KEXT  = LNUM * RNK;   // 128
// SCALE = lora_alpha / lora_rank = 2.0

// GEMM tiling (Ampere-style mma.sync path — tcgen05 is sm_103a-gated and the
// harness compiles PTX at family target sm_103, so it is unavailable).
static constexpr int BM = 128;
static constexpr int BN = 128;
static constexpr int BK = 32;              // 32 tf32 per K-tile
static constexpr int STAGES = 4;

// Shared memory: per stage A[128][36] + B[128][36] floats (pad 32->36:
// fragment LDS bank = (36*g + c) % 32 = (4g + c) % 32, conflict-free).
static constexpr int ROW_PAD = 36;
static constexpr int A_FLOATS = BM * ROW_PAD;              // 4608
static constexpr int STG_FLOATS = 2 * A_FLOATS;            // 9216
static constexpr int SMEM_BYTES = STAGES * STG_FLOATS * 4; // 147456

// ============================================================================
// Scratch (allocation-free: __device__ globals)
// ============================================================================
__device__ __align__(128) float g_u[(size_t)N_TOK * KEXT];     // masked+scaled x@A_cat^T
__device__ __align__(128) float g_bcat[(size_t)DOUT * KEXT];   // B_all -> [DOUT, 128]

// ============================================================================
// PTX helpers (all family-wide sm_80+ features; nothing 'a'-gated)
// ============================================================================
__device__ __forceinline__ uint32_t smem_to_u32(const void* p) {
    uint32_t a;
    asm("{ .reg .u64 t; cvta.to.shared.u64 t, %1; cvt.u32.u64 %0, t; }" : "=r"(a) : "l"(p));
    return a;
}

#define CP_ASYNC16(dst_u32, src_ptr) \
    asm volatile("cp.async.cg.shared.global [%0], [%1], 16;" \
                 :: "r"(dst_u32), "l"(src_ptr) : "memory")
#define CP_COMMIT() asm volatile("cp.async.commit_group;" ::: "memory")
#define CP_WAIT(n)  asm volatile("cp.async.wait_group %0;" :: "n"(n) : "memory")

// Unbiased fp32 -> tf32 (round-to-nearest). Raw-bit truncation would give a
// systematic ~2^-10 relative bias over K=2176 — over the 1e-3 budget.
__device__ __forceinline__ uint32_t f2tf32(float f) {
    uint32_t r;
    asm("cvt.rna.tf32.f32 %0, %1;" : "=r"(r) : "f"(f));
    return r;
}

__device__ __forceinline__ void mma_tf32(float* d, const uint32_t* a, const uint32_t* b) {
    asm volatile(
        "mma.sync.aligned.m16n8k8.row.col.f32.tf32.tf32.f32 "
        "{%0,%1,%2,%3}, {%4,%5,%6,%7}, {%8,%9}, {%0,%1,%2,%3};"
        : "+f"(d[0]), "+f"(d[1]), "+f"(d[2]), "+f"(d[3])
        : "r"(a[0]), "r"(a[1]), "r"(a[2]), "r"(a[3]),
          "r"(b[0]), "r"(b[1]));
}

// ============================================================================
// B_all [L, DOUT, R] -> g_bcat [DOUT, L*R]
// ============================================================================
__global__ void bcat_kernel(const float* __restrict__ B_all, float* __restrict__ bcat) {
    int t = blockIdx.x * blockDim.x + threadIdx.x;
    if (t >= DOUT * KEXT) return;
    int o = t >> 7;          // output feature
    int j = t & 127;         // l*16 + r
    int l = j >> 4;
    int r = j & 15;
    bcat[t] = B_all[((size_t)l * DOUT + o) * RNK + r];
}

// ============================================================================
// tf32 mma.sync GEMM:  D[m,n] = sum_k A[m,k]*B[n,k]  (both K-major)
//   A rows m0..m0+127: gA0 (pitch pA0) for k-tile < KMAIN, else gA1 (pitch KEXT)
//   B rows n0..n0+127: gB0 (pitch pB0) for k-tile < KMAIN, else gB1 (pitch KEXT)
// EPI 0: out[row*DOUT + col] = D + bias[col]
// EPI 1: out[row*KEXT + col] = ((col>>4) == lidx[row]) ? 2*D : 0
// 256 threads, warps 2(M) x 4(N), warp tile 64x32, 1 CTA/SM.
// ============================================================================
template <int KTOT, int KMAIN, int EPI>
__global__ void __launch_bounds__(256, 1) gemm_kernel(
    const float* __restrict__ gA0, const float* __restrict__ gA1, int pA0,
    const float* __restrict__ gB0, const float* __restrict__ gB1, int pB0,
    const float* __restrict__ bias,
    const int*   __restrict__ lidx,
    float*       __restrict__ out,
    int tiles_n)
{
    extern __shared__ float smf[];

    const int tid  = threadIdx.x;
    const int lane = tid & 31;
    const int wid  = tid >> 5;
    const int wm   = wid & 1;    // warp M index (0..1)
    const int wn   = wid >> 1;   // warp N index (0..3)
    const int g    = lane >> 2;  // groupID (0..7)
    const int c    = lane & 3;   // threadID in group (0..3)

    // Band rasterization: 8 m-tiles x tiles_n per band (keeps W L2-resident).
    const int per_band = 8 * tiles_n;
    const int band = blockIdx.x / per_band;
    const int idx  = blockIdx.x % per_band;
    const int mt   = band * 8 + (idx % 8);
    const int nt   = idx / 8;
    const int m0   = mt * BM;
    const int n0   = nt * BN;

    // cp.async mapping: thread t loads 16B chunks; 32 rows x 8 chunks per pass,
    // 4 passes cover 128 rows (for each of A and B).
    const int ldr = tid >> 3;        // base row 0..31
    const int ldc = (tid & 7) * 4;   // float column 0,4,...,28

    const uint32_t sb = smem_to_u32(smf);

    float acc[4][4][4];
    #pragma unroll
    for (int i = 0; i < 4; i++)
        #pragma unroll
        for (int j = 0; j < 4; j++)
            #pragma unroll
            for (int q = 0; q < 4; q++) acc[i][j][q] = 0.0f;

    // ---- stage loader ----
    auto load_stage = [&](int k, int s) {
        const uint32_t sa = sb + (uint32_t)(s * STG_FLOATS) * 4u;
        const uint32_t sbb = sa + (uint32_t)A_FLOATS * 4u;
        const float* srcA;
        const float* srcB;
        int pa, pb;
        if (k < KMAIN) {
            srcA = gA0 + (size_t)(m0 + ldr) * pA0 + k * BK + ldc; pa = pA0;
            srcB = gB0 + (size_t)(n0 + ldr) * pB0 + k * BK + ldc; pb = pB0;
        } else {
            srcA = gA1 + (size_t)(m0 + ldr) * KEXT + (k - KMAIN) * BK + ldc; pa = KEXT;
            srcB = gB1 + (size_t)(n0 + ldr) * KEXT + (k - KMAIN) * BK + ldc; pb = KEXT;
        }
        #pragma unroll
        for (int i = 0; i < 4; i++) {
            CP_ASYNC16(sa  + (uint32_t)(((ldr + i * 32) * ROW_PAD + ldc) * 4), srcA + (size_t)i * 32 * pa);
            CP_ASYNC16(sbb + (uint32_t)(((ldr + i * 32) * ROW_PAD + ldc) * 4), srcB + (size_t)i * 32 * pb);
        }
    };

    // ---- prologue: fill STAGES-1 stages ----
    #pragma unroll
    for (int s = 0; s < STAGES - 1; s++) {
        load_stage(s, s);
        CP_COMMIT();
    }

    // ---- main loop ----
    for (int k = 0; k < KTOT; k++) {
        CP_WAIT(STAGES - 2);
        __syncthreads();

        // issue next stage (overwrites stage read at iter k-1; barrier protects)
        if (k + STAGES - 1 < KTOT) load_stage(k + STAGES - 1, (k + STAGES - 1) % STAGES);
        CP_COMMIT();

        const float* As = smf + (size_t)(k % STAGES) * STG_FLOATS;
        const float* Bs = As + A_FLOATS;

        #pragma unroll
        for (int ks = 0; ks < 4; ks++) {
            uint32_t af[4][4], bf[4][2];
            const int kc = ks * 8 + c;
            #pragma unroll
            for (int mi = 0; mi < 4; mi++) {
                int r = wm * 64 + mi * 16 + g;
                af[mi][0] = f2tf32(As[r * ROW_PAD + kc]);
                af[mi][1] = f2tf32(As[(r + 8) * ROW_PAD + kc]);
                af[mi][2] = f2tf32(As[r * ROW_PAD + kc + 4]);
                af[mi][3] = f2tf32(As[(r + 8) * ROW_PAD + kc + 4]);
            }
            #pragma unroll
            for (int ni = 0; ni < 4; ni++) {
                int rn = wn * 32 + ni * 8 + g;
                bf[ni][0] = f2tf32(Bs[rn * ROW_PAD + kc]);
                bf[ni][1] = f2tf32(Bs[rn * ROW_PAD + kc + 4]);
            }
            #pragma unroll
            for (int mi = 0; mi < 4; mi++)
                #pragma unroll
                for (int ni = 0; ni < 4; ni++)
                    mma_tf32(acc[mi][ni], af[mi], bf[ni]);
        }
    }

    CP_WAIT(0);

    // ---- epilogue ----
    #pragma unroll
    for (int mi = 0; mi < 4; mi++) {
        int row = m0 + wm * 64 + mi * 16 + g;
        if constexpr (EPI == 0) {
            #pragma unroll
            for (int h = 0; h < 2; h++) {
                size_t rbase = (size_t)(row + h * 8) * DOUT;
                #pragma unroll
                for (int ni = 0; ni < 4; ni++) {
                    int col = n0 + wn * 32 + ni * 8 + 2 * c;
                    float2 bv = *reinterpret_cast<const float2*>(bias + col);
                    float2 o;
                    o.x = acc[mi][ni][h * 2 + 0] + bv.x;
                    o.y = acc[mi][ni][h * 2 + 1] + bv.y;
                    *reinterpret_cast<float2*>(out + rbase + col) = o;
                }
            }
        } else {
            int li0 = lidx[row];
            int li1 = lidx[row + 8];
            #pragma unroll
            for (int ni = 0; ni < 4; ni++) {
                int col = wn * 32 + ni * 8 + 2 * c;   // n0 == 0 for prep GEMM
                int grp = col >> 4;                    // col, col+1 share grp (col even)
                float s0 = (grp == li0) ? 2.0f : 0.0f;
                float s1 = (grp == li1) ? 2.0f : 0.0f;
                float2 o0, o1;
                o0.x = acc[mi][ni][0] * s0; o0.y = acc[mi][ni][1] * s0;
                o1.x = acc[mi][ni][2] * s1; o1.y = acc[mi][ni][3] * s1;
                *reinterpret_cast<float2*>(out + (size_t)row * KEXT + col) = o0;
                *reinterpret_cast<float2*>(out + (size_t)(row + 8) * KEXT + col) = o1;
            }
        }
    }
}

// ============================================================================
// Host side
// ============================================================================
extern "C" void kernel_launch(void* const* d_in, const int* in_sizes, int n_in,
                              void* d_out, int out_size) {
    (void)in_sizes; (void)n_in; (void)out_size;
    const float* x     = (const float*)d_in[0];   // [32768, 2048]
    const float* W     = (const float*)d_in[1];   // [2048, 2048]
    const float* b     = (const float*)d_in[2];   // [2048]
    const float* A_all = (const float*)d_in[3];   // [8, 16, 2048] == A_cat [128, 2048]
    const float* B_all = (const float*)d_in[4];   // [8, 2048, 16]
    const int*   lidx  = (const int*)d_in[5];     // [32768]
    float* out = (float*)d_out;                    // [32768, 2048]

    void *up = nullptr, *cp = nullptr;
    cudaGetSymbolAddress(&up, g_u);
    cudaGetSymbolAddress(&cp, g_bcat);
    float* u  = (float*)up;
    float* bc = (float*)cp;

    // 1) transpose B_all -> g_bcat
    bcat_kernel<<<(DOUT * KEXT + 255) / 256, 256>>>(B_all, bc);

    // 2) prep GEMM: g_u = mask(x @ A_cat^T) * 2    (M=32768, N=128, K=2048)
    cudaFuncSetAttribute((const void*)gemm_kernel<DIN / BK, DIN / BK, 1>,
                         cudaFuncAttributeMaxDynamicSharedMemorySize, SMEM_BYTES);
    gemm_kernel<DIN / BK, DIN / BK, 1><<<N_TOK / BM, 256, SMEM_BYTES>>>(
        x, x, DIN, A_all, A_all, DIN, b, lidx, u, KEXT / BN);

    // 3) main GEMM: out = [x | g_u] @ [W | g_bcat]^T + b   (K = 2048 + 128)
    cudaFuncSetAttribute((const void*)gemm_kernel<(DIN + KEXT) / BK, DIN / BK, 0>,
                         cudaFuncAttributeMaxDynamicSharedMemorySize, SMEM_BYTES);
    gemm_kernel<(DIN + KEXT) / BK, DIN / BK, 0>
        <<<(N_TOK / BM) * (DOUT / BN), 256, SMEM_BYTES>>>(
        x, u, DIN, W, bc, DIN, b, lidx, out, DOUT / BN);
}

// round 6
// speedup vs baseline: 1.0410x; 1.0410x over previous
#include <cuda_runtime.h>
#include <cstdint>
#include <cstddef>

// ============================================================================
// Problem constants
// ============================================================================
static constexpr int N_TOK = 32768;
static constexpr int DIN   = 2048;
static constexpr int DOUT  = 2048;
static constexpr int RNK   = 16;
static constexpr int KEXT  = 128;          // 8 adapters * rank 16
// SCALE = lora_alpha / lora_rank = 2.0

static constexpr int BM = 128;
static constexpr int BK = 32;              // K-tile (one permuted 32-col group)
static constexpr int STAGES = 3;
static constexpr int ROW_PAD = 36;         // floats per smem row (bank-conflict-free LDS.128)

// ============================================================================
// Scratch (__device__ globals, allocation-free)
// All "r" buffers hold tf32-pre-rounded fp32 in COLUMN-PERMUTED layout:
// within each 32-col group, logical col k sits at p = (k%4)*8 + k/4.
// This makes each mma fragment a contiguous float4 in shared memory.
// ============================================================================
__device__ __align__(16) float g_xr[(size_t)N_TOK * DIN];   // x rounded+permuted
__device__ __align__(16) float g_wr[(size_t)DOUT * DIN];    // W rounded+permuted
__device__ __align__(16) float g_ar[(size_t)KEXT * DIN];    // A_cat rounded+permuted
__device__ __align__(16) float g_bc[(size_t)DOUT * KEXT];   // B_all^T rounded+permuted
__device__ __align__(16) float g_u [(size_t)N_TOK * KEXT];  // masked 2*(x@A^T), rounded+permuted

// ============================================================================
// PTX helpers (family-wide sm_80+ only; nothing 'a'-gated)
// ============================================================================
__device__ __forceinline__ uint32_t smem_to_u32(const void* p) {
    uint32_t a;
    asm("{ .reg .u64 t; cvta.to.shared.u64 t, %1; cvt.u32.u64 %0, t; }" : "=r"(a) : "l"(p));
    return a;
}

#define CP_ASYNC16(dst_u32, src_ptr) \
    asm volatile("cp.async.cg.shared.global [%0], [%1], 16;" \
                 :: "r"(dst_u32), "l"(src_ptr) : "memory")
#define CP_COMMIT() asm volatile("cp.async.commit_group;" ::: "memory")
#define CP_WAIT(n)  asm volatile("cp.async.wait_group %0;" :: "n"(n) : "memory")

// Unbiased fp32 -> tf32 (round-to-nearest); result has low 13 bits zero, so
// the HMMA's truncating conversion is exact on it.
__device__ __forceinline__ float f2tf32f(float f) {
    uint32_t r;
    asm("cvt.rna.tf32.f32 %0, %1;" : "=r"(r) : "f"(f));
    return __uint_as_float(r);
}

__device__ __forceinline__ void mma_tf32(float* d, const uint32_t* a, const uint32_t* b) {
    asm volatile(
        "mma.sync.aligned.m16n8k8.row.col.f32.tf32.tf32.f32 "
        "{%0,%1,%2,%3}, {%4,%5,%6,%7}, {%8,%9}, {%0,%1,%2,%3};"
        : "+f"(d[0]), "+f"(d[1]), "+f"(d[2]), "+f"(d[3])
        : "r"(a[0]), "r"(a[1]), "r"(a[2]), "r"(a[3]),
          "r"(b[0]), "r"(b[1]));
}

// ============================================================================
// Round + permute copy: dst[group*32 + (j%4)*8 + j/4] = rna_tf32(src[i])
// ============================================================================
__global__ void round_perm_kernel(const float* __restrict__ src, float* __restrict__ dst, int n) {
    int i = blockIdx.x * blockDim.x + threadIdx.x;
    if (i >= n) return;
    int base = i & ~31;
    int j = i & 31;
    int p = (j & 3) * 8 + (j >> 2);
    dst[base + p] = f2tf32f(src[i]);
}

// B_all [L, DOUT, R] -> g_bc [DOUT, 128] rounded + permuted
__global__ void bcat_kernel(const float* __restrict__ B_all, float* __restrict__ bc) {
    int t = blockIdx.x * blockDim.x + threadIdx.x;
    if (t >= DOUT * KEXT) return;
    int o = t >> 7;
    int j = t & 127;
    int l = j >> 4, r = j & 15;
    float v = B_all[((size_t)l * DOUT + o) * RNK + r];
    int jj = j & 31;
    int p = (j & ~31) + (jj & 3) * 8 + (jj >> 2);
    bc[o * KEXT + p] = f2tf32f(v);
}

// ============================================================================
// tf32 mma.sync GEMM:  D[m,n] = sum_k A[m,k]*B[n,k]  (pre-rounded, permuted)
//   A rows: gA0 (pitch pA0) for k-tile < KMAIN, else gA1 (pitch KEXT)
//   B rows: gB0 (pitch pB0) for k-tile < KMAIN, else gB1 (pitch KEXT)
// EPI 0: out[row*DOUT + col] = D + bias[col]          (plain fp32 layout)
// EPI 1: out[row*KEXT + perm(col)] = masked 2*D, rounded (feeds main GEMM)
// 256 threads = 8 warps, 2(M) x 4(N); warp tile 64 x (BN/4); 1 CTA/SM.
// ============================================================================
template <int BN, int KTOT, int KMAIN, int EPI>
__global__ void __launch_bounds__(256, 1) gemm_kernel(
    const float* __restrict__ gA0, const float* __restrict__ gA1, int pA0,
    const float* __restrict__ gB0, const float* __restrict__ gB1, int pB0,
    const float* __restrict__ bias,
    const int*   __restrict__ lidx,
    float*       __restrict__ out,
    int tiles_n)
{
    constexpr int NI = BN / 32;                    // n-subtiles per warp
    constexpr int A_FLOATS = BM * ROW_PAD;
    constexpr int STG_FLOATS = (BM + BN) * ROW_PAD;

    extern __shared__ float smf[];

    const int tid  = threadIdx.x;
    const int lane = tid & 31;
    const int wid  = tid >> 5;
    const int wm   = wid & 1;
    const int wn   = wid >> 1;
    const int g    = lane >> 2;   // 0..7
    const int c    = lane & 3;    // 0..3

    // band rasterization: 16 m-tiles x tiles_n per band (W stays L2-resident)
    const int per_band = 16 * tiles_n;
    const int band = blockIdx.x / per_band;
    const int idx  = blockIdx.x % per_band;
    const int mt   = band * 16 + (idx % 16);
    const int nt   = idx / 16;
    const int m0   = mt * BM;
    const int n0   = nt * BN;

    // cp.async mapping: 16B chunks, 32 rows x 8 chunks per pass
    const int ldr = tid >> 3;
    const int ldc = (tid & 7) * 4;

    const uint32_t sb = smem_to_u32(smf);

    float acc[4][NI][4];
    #pragma unroll
    for (int i = 0; i < 4; i++)
        #pragma unroll
        for (int j = 0; j < NI; j++)
            #pragma unroll
            for (int q = 0; q < 4; q++) acc[i][j][q] = 0.0f;

    auto load_stage = [&](int kt, int s) {
        const uint32_t sa  = sb + (uint32_t)(s * STG_FLOATS) * 4u;
        const uint32_t sbB = sa + (uint32_t)A_FLOATS * 4u;
        const float* srcA;
        const float* srcB;
        int pa, pb;
        if (kt < KMAIN) {
            srcA = gA0 + (size_t)(m0 + ldr) * pA0 + kt * BK + ldc; pa = pA0;
            srcB = gB0 + (size_t)(n0 + ldr) * pB0 + kt * BK + ldc; pb = pB0;
        } else {
            srcA = gA1 + (size_t)(m0 + ldr) * KEXT + (kt - KMAIN) * BK + ldc; pa = KEXT;
            srcB = gB1 + (size_t)(n0 + ldr) * KEXT + (kt - KMAIN) * BK + ldc; pb = KEXT;
        }
        #pragma unroll
        for (int i = 0; i < BM / 32; i++)
            CP_ASYNC16(sa  + (uint32_t)(((ldr + i * 32) * ROW_PAD + ldc) * 4), srcA + (size_t)i * 32 * pa);
        #pragma unroll
        for (int i = 0; i < BN / 32; i++)
            CP_ASYNC16(sbB + (uint32_t)(((ldr + i * 32) * ROW_PAD + ldc) * 4), srcB + (size_t)i * 32 * pb);
    };

    #pragma unroll
    for (int s = 0; s < STAGES - 1; s++) {
        load_stage(s, s);
        CP_COMMIT();
    }

    for (int kt = 0; kt < KTOT; kt++) {
        CP_WAIT(STAGES - 2);
        __syncthreads();

        if (kt + STAGES - 1 < KTOT) load_stage(kt + STAGES - 1, (kt + STAGES - 1) % STAGES);
        CP_COMMIT();

        const float* As = smf + (size_t)(kt % STAGES) * STG_FLOATS;
        const float* Bs = As + A_FLOATS;

        #pragma unroll
        for (int half = 0; half < 2; half++) {
            // Permuted layout: float4 at [row][c*8 + half*4] holds, for
            // ks = 2*half + {0,1}: (f0,f1)=ks0 (k, k+4), (f2,f3)=ks1 (k, k+4).
            float4 aLo[4], aHi[4];
            #pragma unroll
            for (int mi = 0; mi < 4; mi++) {
                int r = wm * 64 + mi * 16 + g;
                aLo[mi] = *reinterpret_cast<const float4*>(As + r * ROW_PAD + c * 8 + half * 4);
                aHi[mi] = *reinterpret_cast<const float4*>(As + (r + 8) * ROW_PAD + c * 8 + half * 4);
            }
            float4 bV[NI];
            #pragma unroll
            for (int ni = 0; ni < NI; ni++) {
                int rn = wn * (BN / 4) + ni * 8 + g;
                bV[ni] = *reinterpret_cast<const float4*>(Bs + rn * ROW_PAD + c * 8 + half * 4);
            }
            #pragma unroll
            for (int ks2 = 0; ks2 < 2; ks2++) {
                #pragma unroll
                for (int mi = 0; mi < 4; mi++) {
                    const float* lo = reinterpret_cast<const float*>(&aLo[mi]);
                    const float* hi = reinterpret_cast<const float*>(&aHi[mi]);
                    uint32_t a[4];
                    a[0] = __float_as_uint(lo[2 * ks2 + 0]);
                    a[1] = __float_as_uint(hi[2 * ks2 + 0]);
                    a[2] = __float_as_uint(lo[2 * ks2 + 1]);
                    a[3] = __float_as_uint(hi[2 * ks2 + 1]);
                    #pragma unroll
                    for (int ni = 0; ni < NI; ni++) {
                        const float* bp = reinterpret_cast<const float*>(&bV[ni]);
                        uint32_t bb[2];
                        bb[0] = __float_as_uint(bp[2 * ks2 + 0]);
                        bb[1] = __float_as_uint(bp[2 * ks2 + 1]);
                        mma_tf32(acc[mi][ni], a, bb);
                    }
                }
            }
        }
    }

    CP_WAIT(0);

    // ---- epilogue ----
    if constexpr (EPI == 0) {
        float2 bv[NI];
        #pragma unroll
        for (int ni = 0; ni < NI; ni++)
            bv[ni] = *reinterpret_cast<const float2*>(bias + n0 + wn * (BN / 4) + ni * 8 + 2 * c);
        #pragma unroll
        for (int mi = 0; mi < 4; mi++) {
            int row = m0 + wm * 64 + mi * 16 + g;
            #pragma unroll
            for (int h = 0; h < 2; h++) {
                size_t rbase = (size_t)(row + h * 8) * DOUT;
                #pragma unroll
                for (int ni = 0; ni < NI; ni++) {
                    int col = n0 + wn * (BN / 4) + ni * 8 + 2 * c;
                    float2 o;
                    o.x = acc[mi][ni][h * 2 + 0] + bv[ni].x;
                    o.y = acc[mi][ni][h * 2 + 1] + bv[ni].y;
                    *reinterpret_cast<float2*>(out + rbase + col) = o;
                }
            }
        }
    } else {
        // masked, scaled, rounded, permuted scatter into g_u
        #pragma unroll
        for (int mi = 0; mi < 4; mi++) {
            int row = m0 + wm * 64 + mi * 16 + g;
            int li0 = lidx[row];
            int li1 = lidx[row + 8];
            #pragma unroll
            for (int ni = 0; ni < NI; ni++) {
                #pragma unroll
                for (int q = 0; q < 2; q++) {
                    int j = wn * (BN / 4) + ni * 8 + 2 * c + q;   // logical col 0..127
                    int grp = j >> 4;
                    int jj = j & 31;
                    int p = (j & ~31) + (jj & 3) * 8 + (jj >> 2);
                    float v0 = (grp == li0) ? f2tf32f(2.0f * acc[mi][ni][q])     : 0.0f;
                    float v1 = (grp == li1) ? f2tf32f(2.0f * acc[mi][ni][2 + q]) : 0.0f;
                    out[(size_t)row * KEXT + p] = v0;
                    out[(size_t)(row + 8) * KEXT + p] = v1;
                }
            }
        }
    }
}

// ============================================================================
// Host side
// ============================================================================
extern "C" void kernel_launch(void* const* d_in, const int* in_sizes, int n_in,
                              void* d_out, int out_size) {
    (void)in_sizes; (void)n_in; (void)out_size;
    const float* x     = (const float*)d_in[0];   // [32768, 2048]
    const float* W     = (const float*)d_in[1];   // [2048, 2048]
    const float* b     = (const float*)d_in[2];   // [2048]
    const float* A_all = (const float*)d_in[3];   // [8, 16, 2048] == A_cat [128, 2048]
    const float* B_all = (const float*)d_in[4];   // [8, 2048, 16]
    const int*   lidx  = (const int*)d_in[5];     // [32768]
    float* out = (float*)d_out;                    // [32768, 2048]

    void *xp, *wp, *ap, *cp, *up;
    cudaGetSymbolAddress(&xp, g_xr);
    cudaGetSymbolAddress(&wp, g_wr);
    cudaGetSymbolAddress(&ap, g_ar);
    cudaGetSymbolAddress(&cp, g_bc);
    cudaGetSymbolAddress(&up, g_u);
    float* xr = (float*)xp;
    float* wr = (float*)wp;
    float* ar = (float*)ap;
    float* bc = (float*)cp;
    float* u  = (float*)up;

    // 1) round + permute operands
    round_perm_kernel<<<(N_TOK * DIN) / 256, 256>>>(x, xr, N_TOK * DIN);
    round_perm_kernel<<<(DOUT * DIN) / 256, 256>>>(W, wr, DOUT * DIN);
    round_perm_kernel<<<(KEXT * DIN) / 256, 256>>>(A_all, ar, KEXT * DIN);
    bcat_kernel<<<(DOUT * KEXT + 255) / 256, 256>>>(B_all, bc);

    // 2) prep GEMM: g_u = perm(round(mask(x @ A_cat^T) * 2))   (N=128, K=2048)
    {
        constexpr int SMEM = STAGES * (BM + 128) * ROW_PAD * 4;   // 110592
        cudaFuncSetAttribute((const void*)gemm_kernel<128, DIN / BK, DIN / BK, 1>,
                             cudaFuncAttributeMaxDynamicSharedMemorySize, SMEM);
        gemm_kernel<128, DIN / BK, DIN / BK, 1><<<N_TOK / BM, 256, SMEM>>>(
            xr, xr, DIN, ar, ar, DIN, b, lidx, u, 1);
    }

    // 3) main GEMM: out = [x | u] @ [W | bcat]^T + b   (N=2048 in BN=256 tiles, K=2176)
    {
        constexpr int SMEM = STAGES * (BM + 256) * ROW_PAD * 4;   // 165888
        cudaFuncSetAttribute((const void*)gemm_kernel<256, (DIN + KEXT) / BK, DIN / BK, 0>,
                             cudaFuncAttributeMaxDynamicSharedMemorySize, SMEM);
        gemm_kernel<256, (DIN + KEXT) / BK, DIN / BK, 0>
            <<<(N_TOK / BM) * (DOUT / 256), 256, SMEM>>>(
            xr, u, DIN, wr, bc, DIN, b, lidx, out, DOUT / 256);
    }
}

// round 7
// speedup vs baseline: 2.0193x; 1.9397x over previous
#include <cuda_runtime.h>
#include <cuda_fp16.h>
#include <cstdint>
#include <cstddef>

// ============================================================================
// Problem constants
// ============================================================================
static constexpr int N_TOK = 32768;
static constexpr int DIN   = 2048;
static constexpr int DOUT  = 2048;
static constexpr int KEXT  = 128;          // 8 adapters * rank 16
// SCALE = lora_alpha / lora_rank = 2.0

static constexpr int BM = 128;
static constexpr int STAGES = 4;

// ============================================================================
// Scratch (__device__ globals, allocation-free).
// All half buffers are in FRAGMENT-LINEAR layout: matrix split into 16x16
// blocks (block-row-major, k-blocks contiguous per row-block); inside a block
// the 256 halfs are stored in (lane, fragment-reg) order for mma.m16n8k16, so
// one LDS.128 per lane fetches a whole fragment.
//  A-operand layout (x, u):  j = (hk*2 + hm)*2 + lo   (a0,a1,a2,a3 order)
//  B-operand layout (W, A_cat, bcat): j = hn*4 + hk*2 + lo
// ============================================================================
__device__ __align__(16) __half g_xh [(size_t)N_TOK * DIN];   // x
__device__ __align__(16) __half g_wh [(size_t)DOUT * DIN];    // W
__device__ __align__(16) __half g_ah [(size_t)KEXT * DIN];    // A_cat
__device__ __align__(16) __half g_bch[(size_t)DOUT * KEXT];   // B_all^T
__device__ __align__(16) __half g_uh [(size_t)N_TOK * KEXT];  // masked 2*(x@A^T)

// ============================================================================
// PTX helpers (family-wide sm_80+; nothing architecture-'a'-gated)
// ============================================================================
__device__ __forceinline__ uint32_t smem_to_u32(const void* p) {
    uint32_t a;
    asm("{ .reg .u64 t; cvta.to.shared.u64 t, %1; cvt.u32.u64 %0, t; }" : "=r"(a) : "l"(p));
    return a;
}

#define CP_ASYNC16(dst_u32, src_ptr) \
    asm volatile("cp.async.cg.shared.global [%0], [%1], 16;" \
                 :: "r"(dst_u32), "l"(src_ptr) : "memory")
#define CP_COMMIT() asm volatile("cp.async.commit_group;" ::: "memory")
#define CP_WAIT(n)  asm volatile("cp.async.wait_group %0;" :: "n"(n) : "memory")

__device__ __forceinline__ void mma_f16(float* d, const uint4& a, uint32_t b0, uint32_t b1) {
    asm volatile(
        "mma.sync.aligned.m16n8k16.row.col.f32.f16.f16.f32 "
        "{%0,%1,%2,%3}, {%4,%5,%6,%7}, {%8,%9}, {%0,%1,%2,%3};"
        : "+f"(d[0]), "+f"(d[1]), "+f"(d[2]), "+f"(d[3])
        : "r"(a.x), "r"(a.y), "r"(a.z), "r"(a.w), "r"(b0), "r"(b1));
}

// ============================================================================
// Conversion kernels: fp32 row-major -> fp16 fragment-linear
// ============================================================================
template <int K>
__global__ void conv_a_kernel(const float* __restrict__ src, __half* __restrict__ dst, int M) {
    int i = blockIdx.x * blockDim.x + threadIdx.x;     // over M*K/2, k-pairs
    if (i >= M * (K / 2)) return;
    int m = i / (K / 2);
    int k = (i % (K / 2)) * 2;
    float2 v = *reinterpret_cast<const float2*>(src + (size_t)m * K + k);
    int mb = m >> 4, mr = m & 15, kb = k >> 4, kr = k & 15;
    int g = mr & 7, hm = mr >> 3;
    int c = (kr >> 1) & 3, hk = kr >> 3;
    size_t off = ((size_t)mb * (K / 16) + kb) * 256 + (g * 4 + c) * 8 + (hk * 2 + hm) * 2;
    *reinterpret_cast<__half2*>(dst + off) = __floats2half2_rn(v.x, v.y);
}

template <int K>
__global__ void conv_b_kernel(const float* __restrict__ src, __half* __restrict__ dst, int Nr) {
    int i = blockIdx.x * blockDim.x + threadIdx.x;     // over Nr*K/2
    if (i >= Nr * (K / 2)) return;
    int n = i / (K / 2);
    int k = (i % (K / 2)) * 2;
    float2 v = *reinterpret_cast<const float2*>(src + (size_t)n * K + k);
    int nb = n >> 4, nr = n & 15, kb = k >> 4, kr = k & 15;
    int g = nr & 7, hn = nr >> 3;
    int c = (kr >> 1) & 3, hk = kr >> 3;
    size_t off = ((size_t)nb * (K / 16) + kb) * 256 + (g * 4 + c) * 8 + hn * 4 + hk * 2;
    *reinterpret_cast<__half2*>(dst + off) = __floats2half2_rn(v.x, v.y);
}

// B_all [L, DOUT, 16] -> bcat rows n=o, cols k=l*16+r, B-frag-linear, K=KEXT
__global__ void conv_bcat_kernel(const float* __restrict__ B_all, __half* __restrict__ dst) {
    int i = blockIdx.x * blockDim.x + threadIdx.x;     // over DOUT*64
    if (i >= DOUT * (KEXT / 2)) return;
    int o = i >> 6;
    int k = (i & 63) * 2;
    int l = k >> 4, r = k & 15;
    float2 v = *reinterpret_cast<const float2*>(B_all + ((size_t)l * DOUT + o) * 16 + r);
    int nb = o >> 4, nr = o & 15, kb = k >> 4, kr = k & 15;
    int g = nr & 7, hn = nr >> 3;
    int c = (kr >> 1) & 3, hk = kr >> 3;
    size_t off = ((size_t)nb * (KEXT / 16) + kb) * 256 + (g * 4 + c) * 8 + hn * 4 + hk * 2;
    *reinterpret_cast<__half2*>(dst + off) = __floats2half2_rn(v.x, v.y);
}

// ============================================================================
// fp16 mma.sync GEMM on fragment-linear operands.
//   D[m,n] = sum_k A[m,k]*B[n,k]
//   A blocks: gA0 (pitch pA0 k-blocks) for kt < KMAIN, else gA1 (pitch pA1)
//   B blocks: gB0 / gB1 likewise.
// EPI 0: float out[row*DOUT + col] = D + bias[col]
// EPI 1: half  out = A-frag-linear( masked 2*D )   (feeds main GEMM as gA1)
// 256 threads = 8 warps (2 M x 4 N); warp tile 64 x (BN/4); 1 CTA/SM.
// ============================================================================
template <int BN, int KTOT, int KMAIN, int EPI>
__global__ void __launch_bounds__(256, 1) gemm_f16_kernel(
    const __half* __restrict__ gA0, const __half* __restrict__ gA1, int pA0, int pA1,
    const __half* __restrict__ gB0, const __half* __restrict__ gB1, int pB0, int pB1,
    const float* __restrict__ bias, const int* __restrict__ lidx,
    void* __restrict__ outv, int tiles_n)
{
    constexpr int NB = BN / 64;                 // 16n-blocks per warp
    constexpr int NI = BN / 32;                 // 8n mma tiles per warp
    constexpr int A_BYTES = 16 * 512;           // (BM/16)*2 blocks * 512 B
    constexpr int B_BYTES = (BN / 16) * 2 * 512;
    constexpr int STG = A_BYTES + B_BYTES;

    extern __shared__ char smc[];
    const uint32_t sb = smem_to_u32(smc);

    const int tid  = threadIdx.x;
    const int lane = tid & 31;
    const int wid  = tid >> 5;
    const int wm   = wid & 1;
    const int wn   = wid >> 1;
    const int g    = lane >> 2;
    const int c    = lane & 3;

    // band rasterization: 16 m-tiles x tiles_n per band (keeps B L2-resident)
    const int per_band = 16 * tiles_n;
    const int band = blockIdx.x / per_band;
    const int idx  = blockIdx.x % per_band;
    const int mt   = band * 16 + (idx % 16);
    const int nt   = idx / 16;
    const int m0b  = mt * (BM / 16);            // in 16-row blocks
    const int n0b  = nt * (BN / 16);

    float acc[4][NI][4];
    #pragma unroll
    for (int i = 0; i < 4; i++)
        #pragma unroll
        for (int j = 0; j < NI; j++)
            #pragma unroll
            for (int q = 0; q < 4; q++) acc[i][j][q] = 0.0f;

    auto load_stage = [&](int kt, int s) {
        const uint32_t st = sb + s * STG;
        #pragma unroll
        for (int j = 0; j < 2; j++) {           // A: 512 chunks / 256 threads
            int q = tid * 2 + j;
            int blk = q >> 5, off = q & 31;
            int kG = kt * 2 + (blk & 1);
            const __half* src = (kt < KMAIN)
                ? gA0 + (((size_t)(m0b + (blk >> 1)) * pA0 + kG) << 8) + off * 8
                : gA1 + (((size_t)(m0b + (blk >> 1)) * pA1 + (kG - KMAIN * 2)) << 8) + off * 8;
            CP_ASYNC16(st + blk * 512 + off * 16, src);
        }
        #pragma unroll
        for (int j = 0; j < NB; j++) {          // B: BN*4 chunks / 256 threads
            int q = tid * NB + j;
            int blk = q >> 5, off = q & 31;
            int kG = kt * 2 + (blk & 1);
            const __half* src = (kt < KMAIN)
                ? gB0 + (((size_t)(n0b + (blk >> 1)) * pB0 + kG) << 8) + off * 8
                : gB1 + (((size_t)(n0b + (blk >> 1)) * pB1 + (kG - KMAIN * 2)) << 8) + off * 8;
            CP_ASYNC16(st + A_BYTES + blk * 512 + off * 16, src);
        }
    };

    #pragma unroll
    for (int s = 0; s < STAGES - 1; s++) { load_stage(s, s); CP_COMMIT(); }

    for (int kt = 0; kt < KTOT; kt++) {
        CP_WAIT(STAGES - 2);
        __syncthreads();
        if (kt + STAGES - 1 < KTOT) load_stage(kt + STAGES - 1, (kt + STAGES - 1) % STAGES);
        CP_COMMIT();

        const char* As = smc + (kt % STAGES) * STG;
        const char* Bs = As + A_BYTES;

        #pragma unroll
        for (int ks = 0; ks < 2; ks++) {
            uint4 af[4], bf[NB];
            #pragma unroll
            for (int mi = 0; mi < 4; mi++)
                af[mi] = *reinterpret_cast<const uint4*>(As + ((wm * 4 + mi) * 2 + ks) * 512 + lane * 16);
            #pragma unroll
            for (int nb = 0; nb < NB; nb++)
                bf[nb] = *reinterpret_cast<const uint4*>(Bs + ((wn * NB + nb) * 2 + ks) * 512 + lane * 16);
            #pragma unroll
            for (int mi = 0; mi < 4; mi++)
                #pragma unroll
                for (int nb = 0; nb < NB; nb++) {
                    mma_f16(acc[mi][2 * nb],     af[mi], bf[nb].x, bf[nb].y);
                    mma_f16(acc[mi][2 * nb + 1], af[mi], bf[nb].z, bf[nb].w);
                }
        }
    }

    // ---- epilogue ----
    if constexpr (EPI == 0) {
        float* out = (float*)outv;
        #pragma unroll
        for (int mi = 0; mi < 4; mi++) {
            int row = (m0b + wm * 4 + mi) * 16 + g;
            #pragma unroll
            for (int ni = 0; ni < NI; ni++) {
                int col = n0b * 16 + wn * (BN / 4) + ni * 8 + 2 * c;
                float2 bv = *reinterpret_cast<const float2*>(bias + col);
                float2 o0, o1;
                o0.x = acc[mi][ni][0] + bv.x; o0.y = acc[mi][ni][1] + bv.y;
                o1.x = acc[mi][ni][2] + bv.x; o1.y = acc[mi][ni][3] + bv.y;
                *reinterpret_cast<float2*>(out + (size_t)row * DOUT + col) = o0;
                *reinterpret_cast<float2*>(out + (size_t)(row + 8) * DOUT + col) = o1;
            }
        }
    } else {
        __half* out = (__half*)outv;   // g_uh, A-frag-linear, K=KEXT
        #pragma unroll
        for (int mi = 0; mi < 4; mi++) {
            int mb = m0b + wm * 4 + mi;
            int row = mb * 16 + g;
            int li0 = lidx[row];
            int li1 = lidx[row + 8];
            #pragma unroll
            for (int ni = 0; ni < NI; ni++) {
                int col = wn * (BN / 4) + ni * 8 + 2 * c;   // n0 == 0 for prep
                int kb = col >> 4;                           // == adapter group
                int hk = ni & 1;
                float s0 = (kb == li0) ? 2.0f : 0.0f;
                float s1 = (kb == li1) ? 2.0f : 0.0f;
                size_t off = ((size_t)mb * (KEXT / 16) + kb) * 256 + (g * 4 + c) * 8 + hk * 4;
                *reinterpret_cast<__half2*>(out + off) =
                    __floats2half2_rn(acc[mi][ni][0] * s0, acc[mi][ni][1] * s0);
                *reinterpret_cast<__half2*>(out + off + 2) =
                    __floats2half2_rn(acc[mi][ni][2] * s1, acc[mi][ni][3] * s1);
            }
        }
    }
}

// ============================================================================
// Host side
// ============================================================================
extern "C" void kernel_launch(void* const* d_in, const int* in_sizes, int n_in,
                              void* d_out, int out_size) {
    (void)in_sizes; (void)n_in; (void)out_size;
    const float* x     = (const float*)d_in[0];   // [32768, 2048]
    const float* W     = (const float*)d_in[1];   // [2048, 2048]
    const float* b     = (const float*)d_in[2];   // [2048]
    const float* A_all = (const float*)d_in[3];   // [8, 16, 2048] == A_cat [128, 2048]
    const float* B_all = (const float*)d_in[4];   // [8, 2048, 16]
    const int*   lidx  = (const int*)d_in[5];     // [32768]
    float* out = (float*)d_out;                    // [32768, 2048]

    void *xp, *wp, *ap, *cp, *up;
    cudaGetSymbolAddress(&xp, g_xh);
    cudaGetSymbolAddress(&wp, g_wh);
    cudaGetSymbolAddress(&ap, g_ah);
    cudaGetSymbolAddress(&cp, g_bch);
    cudaGetSymbolAddress(&up, g_uh);
    __half* xh = (__half*)xp;
    __half* wh = (__half*)wp;
    __half* ah = (__half*)ap;
    __half* bch = (__half*)cp;
    __half* uh = (__half*)up;

    // 1) convert operands to fp16 fragment-linear
    conv_a_kernel<DIN><<<(N_TOK * (DIN / 2) + 255) / 256, 256>>>(x, xh, N_TOK);
    conv_b_kernel<DIN><<<(DOUT * (DIN / 2) + 255) / 256, 256>>>(W, wh, DOUT);
    conv_b_kernel<DIN><<<(KEXT * (DIN / 2) + 255) / 256, 256>>>(A_all, ah, KEXT);
    conv_bcat_kernel<<<(DOUT * (KEXT / 2) + 255) / 256, 256>>>(B_all, bch);

    // 2) prep GEMM: g_uh = Afrag( mask(x @ A_cat^T) * 2 )   (BN=128, K=2048)
    {
        constexpr int SMEM = STAGES * (16 * 512 + (128 / 16) * 2 * 512);  // 65536
        cudaFuncSetAttribute((const void*)gemm_f16_kernel<128, DIN / 32, DIN / 32, 1>,
                             cudaFuncAttributeMaxDynamicSharedMemorySize, SMEM);
        gemm_f16_kernel<128, DIN / 32, DIN / 32, 1><<<N_TOK / BM, 256, SMEM>>>(
            xh, xh, DIN / 16, DIN / 16, ah, ah, DIN / 16, DIN / 16, b, lidx, uh, 1);
    }

    // 3) main GEMM: out = [x | u] @ [W | bcat]^T + b   (BN=256, K=2048+128)
    {
        constexpr int SMEM = STAGES * (16 * 512 + (256 / 16) * 2 * 512);  // 98304
        cudaFuncSetAttribute((const void*)gemm_f16_kernel<256, (DIN + KEXT) / 32, DIN / 32, 0>,
                             cudaFuncAttributeMaxDynamicSharedMemorySize, SMEM);
        gemm_f16_kernel<256, (DIN + KEXT) / 32, DIN / 32, 0>
            <<<(N_TOK / BM) * (DOUT / 256), 256, SMEM>>>(
            xh, uh, DIN / 16, KEXT / 16, wh, bch, DIN / 16, KEXT / 16, b, lidx, out, DOUT / 256);
    }
}

// round 8
// speedup vs baseline: 2.0909x; 1.0354x over previous
#include <cuda_runtime.h>
#include <cuda_fp16.h>
#include <cstdint>
#include <cstddef>

// ============================================================================
// Problem constants
// ============================================================================
static constexpr int N_TOK = 32768;
static constexpr int DIN   = 2048;
static constexpr int DOUT  = 2048;
static constexpr int KEXT  = 128;          // 8 adapters * rank 16
// SCALE = lora_alpha / lora_rank = 2.0

static constexpr int BM = 128;
static constexpr int STAGES = 4;

// ============================================================================
// Scratch (__device__ globals, allocation-free).
// Half buffers in FRAGMENT-LINEAR layout: matrix split into 16x16 blocks
// (block-row-major, k-blocks contiguous per row-block); inside a block the
// 256 halfs are in (lane, fragment-reg) order for mma.m16n8k16 — one LDS.128
// per lane fetches a whole fragment.
//  A-operand (x, u):            lane(g,c) holds rows {g, g+8}, cols {2c,2c+1,2c+8,2c+9}
//  B-operand (W, A_cat, bcat):  lane(g,c) holds cols... rows n {g, g+8} interleaved per 8-n half
// ============================================================================
__device__ __align__(16) __half g_xh [(size_t)N_TOK * DIN];   // x
__device__ __align__(16) __half g_wh [(size_t)DOUT * DIN];    // W
__device__ __align__(16) __half g_ah [(size_t)KEXT * DIN];    // A_cat
__device__ __align__(16) __half g_bch[(size_t)DOUT * KEXT];   // B_all^T
__device__ __align__(16) __half g_uh [(size_t)N_TOK * KEXT];  // masked 2*(x@A^T)

// ============================================================================
// PTX helpers (family-wide sm_80+; nothing architecture-'a'-gated)
// ============================================================================
__device__ __forceinline__ uint32_t smem_to_u32(const void* p) {
    uint32_t a;
    asm("{ .reg .u64 t; cvta.to.shared.u64 t, %1; cvt.u32.u64 %0, t; }" : "=r"(a) : "l"(p));
    return a;
}

#define CP_ASYNC16(dst_u32, src_ptr) \
    asm volatile("cp.async.cg.shared.global [%0], [%1], 16;" \
                 :: "r"(dst_u32), "l"(src_ptr) : "memory")
#define CP_COMMIT() asm volatile("cp.async.commit_group;" ::: "memory")
#define CP_WAIT(n)  asm volatile("cp.async.wait_group %0;" :: "n"(n) : "memory")

__device__ __forceinline__ void mma_f16(float* d, const uint4& a, uint32_t b0, uint32_t b1) {
    asm volatile(
        "mma.sync.aligned.m16n8k16.row.col.f32.f16.f16.f32 "
        "{%0,%1,%2,%3}, {%4,%5,%6,%7}, {%8,%9}, {%0,%1,%2,%3};"
        : "+f"(d[0]), "+f"(d[1]), "+f"(d[2]), "+f"(d[3])
        : "r"(a.x), "r"(a.y), "r"(a.z), "r"(a.w), "r"(b0), "r"(b1));
}

__device__ __forceinline__ uint32_t h2u(__half2 h) { return *reinterpret_cast<uint32_t*>(&h); }

// ============================================================================
// Conversion kernels: fp32 row-major -> fp16 fragment-linear.
// DESTINATION-LINEAR: one thread = one lane fragment = one STG.128.
// Gather loads: 4 consecutive lanes (c=0..3) read 4x8B = one full 32B sector.
// ============================================================================
template <int K>
__global__ void conv_a_lin(const float* __restrict__ src, __half* __restrict__ dst, int nthr) {
    int i = blockIdx.x * blockDim.x + threadIdx.x;     // (M/16)*(K/16)*32 threads
    if (i >= nthr) return;
    int lane = i & 31;
    int blk  = i >> 5;
    constexpr int KB = K / 16;
    int kb = blk % KB, mb = blk / KB;
    int g = lane >> 2, c = lane & 3;
    int r0 = mb * 16 + g;
    int k0 = kb * 16 + c * 2;
    float2 v00 = *reinterpret_cast<const float2*>(src + (size_t)r0 * K + k0);
    float2 v10 = *reinterpret_cast<const float2*>(src + (size_t)(r0 + 8) * K + k0);
    float2 v01 = *reinterpret_cast<const float2*>(src + (size_t)r0 * K + k0 + 8);
    float2 v11 = *reinterpret_cast<const float2*>(src + (size_t)(r0 + 8) * K + k0 + 8);
    uint4 o;   // a0..a7: (r0,klo) (r0+8,klo) (r0,khi) (r0+8,khi)
    o.x = h2u(__floats2half2_rn(v00.x, v00.y));
    o.y = h2u(__floats2half2_rn(v10.x, v10.y));
    o.z = h2u(__floats2half2_rn(v01.x, v01.y));
    o.w = h2u(__floats2half2_rn(v11.x, v11.y));
    *reinterpret_cast<uint4*>(dst + (size_t)blk * 256 + lane * 8) = o;
}

template <int K>
__global__ void conv_b_lin(const float* __restrict__ src, __half* __restrict__ dst, int nthr) {
    int i = blockIdx.x * blockDim.x + threadIdx.x;     // (Nr/16)*(K/16)*32 threads
    if (i >= nthr) return;
    int lane = i & 31;
    int blk  = i >> 5;
    constexpr int KB = K / 16;
    int kb = blk % KB, nb = blk / KB;
    int g = lane >> 2, c = lane & 3;
    int n0 = nb * 16 + g;
    int k0 = kb * 16 + c * 2;
    float2 vn0k0 = *reinterpret_cast<const float2*>(src + (size_t)n0 * K + k0);
    float2 vn0k8 = *reinterpret_cast<const float2*>(src + (size_t)n0 * K + k0 + 8);
    float2 vn8k0 = *reinterpret_cast<const float2*>(src + (size_t)(n0 + 8) * K + k0);
    float2 vn8k8 = *reinterpret_cast<const float2*>(src + (size_t)(n0 + 8) * K + k0 + 8);
    uint4 o;   // [hn=0: b0b1(klo), b2b3(khi)][hn=1: same]
    o.x = h2u(__floats2half2_rn(vn0k0.x, vn0k0.y));
    o.y = h2u(__floats2half2_rn(vn0k8.x, vn0k8.y));
    o.z = h2u(__floats2half2_rn(vn8k0.x, vn8k0.y));
    o.w = h2u(__floats2half2_rn(vn8k8.x, vn8k8.y));
    *reinterpret_cast<uint4*>(dst + (size_t)blk * 256 + lane * 8) = o;
}

// B_all [L, DOUT, 16] -> bcat (rows n=o, cols k=l*16+r), B-frag-linear, K=KEXT
__global__ void conv_bcat_lin(const float* __restrict__ B_all, __half* __restrict__ dst, int nthr) {
    int i = blockIdx.x * blockDim.x + threadIdx.x;     // (DOUT/16)*8*32 threads
    if (i >= nthr) return;
    int lane = i & 31;
    int blk  = i >> 5;
    int l  = blk & 7;            // kb == adapter index
    int nb = blk >> 3;
    int g = lane >> 2, c = lane & 3;
    int o0 = nb * 16 + g;
    int r0 = c * 2;
    float2 vn0k0 = *reinterpret_cast<const float2*>(B_all + ((size_t)l * DOUT + o0) * 16 + r0);
    float2 vn0k8 = *reinterpret_cast<const float2*>(B_all + ((size_t)l * DOUT + o0) * 16 + r0 + 8);
    float2 vn8k0 = *reinterpret_cast<const float2*>(B_all + ((size_t)l * DOUT + o0 + 8) * 16 + r0);
    float2 vn8k8 = *reinterpret_cast<const float2*>(B_all + ((size_t)l * DOUT + o0 + 8) * 16 + r0 + 8);
    uint4 o;
    o.x = h2u(__floats2half2_rn(vn0k0.x, vn0k0.y));
    o.y = h2u(__floats2half2_rn(vn0k8.x, vn0k8.y));
    o.z = h2u(__floats2half2_rn(vn8k0.x, vn8k0.y));
    o.w = h2u(__floats2half2_rn(vn8k8.x, vn8k8.y));
    *reinterpret_cast<uint4*>(dst + (size_t)blk * 256 + lane * 8) = o;
}

// ============================================================================
// fp16 mma.sync GEMM on fragment-linear operands.
//   D[m,n] = sum_k A[m,k]*B[n,k]
//   A blocks: gA0 (pitch pA0 k-blocks) for kt < KMAIN, else gA1 (pitch pA1)
//   B blocks: gB0 / gB1 likewise.
// EPI 0: float out[row*DOUT + col] = D + bias[col]
// EPI 1: half  out = A-frag-linear( masked 2*D )   (feeds main GEMM as gA1)
// 256 threads = 8 warps (2 M x 4 N); warp tile 64 x (BN/4); 1 CTA/SM.
// ============================================================================
template <int BN, int KTOT, int KMAIN, int EPI>
__global__ void __launch_bounds__(256, 1) gemm_f16_kernel(
    const __half* __restrict__ gA0, const __half* __restrict__ gA1, int pA0, int pA1,
    const __half* __restrict__ gB0, const __half* __restrict__ gB1, int pB0, int pB1,
    const float* __restrict__ bias, const int* __restrict__ lidx,
    void* __restrict__ outv, int tiles_n)
{
    constexpr int NB = BN / 64;                 // 16n-blocks per warp
    constexpr int NI = BN / 32;                 // 8n mma tiles per warp
    constexpr int A_BYTES = 16 * 512;           // (BM/16)*2 blocks * 512 B
    constexpr int B_BYTES = (BN / 16) * 2 * 512;
    constexpr int STG = A_BYTES + B_BYTES;

    extern __shared__ char smc[];
    const uint32_t sb = smem_to_u32(smc);

    const int tid  = threadIdx.x;
    const int lane = tid & 31;
    const int wid  = tid >> 5;
    const int wm   = wid & 1;
    const int wn   = wid >> 1;
    const int g    = lane >> 2;
    const int c    = lane & 3;

    // band rasterization: 16 m-tiles x tiles_n per band (keeps B L2-resident)
    const int per_band = 16 * tiles_n;
    const int band = blockIdx.x / per_band;
    const int idx  = blockIdx.x % per_band;
    const int mt   = band * 16 + (idx % 16);
    const int nt   = idx / 16;
    const int m0b  = mt * (BM / 16);            // in 16-row blocks
    const int n0b  = nt * (BN / 16);

    float acc[4][NI][4];
    #pragma unroll
    for (int i = 0; i < 4; i++)
        #pragma unroll
        for (int j = 0; j < NI; j++)
            #pragma unroll
            for (int q = 0; q < 4; q++) acc[i][j][q] = 0.0f;

    auto load_stage = [&](int kt, int s) {
        const uint32_t st = sb + s * STG;
        #pragma unroll
        for (int j = 0; j < 2; j++) {           // A: 512 chunks / 256 threads
            int q = tid * 2 + j;
            int blk = q >> 5, off = q & 31;
            int kG = kt * 2 + (blk & 1);
            const __half* src = (kt < KMAIN)
                ? gA0 + (((size_t)(m0b + (blk >> 1)) * pA0 + kG) << 8) + off * 8
                : gA1 + (((size_t)(m0b + (blk >> 1)) * pA1 + (kG - KMAIN * 2)) << 8) + off * 8;
            CP_ASYNC16(st + blk * 512 + off * 16, src);
        }
        #pragma unroll
        for (int j = 0; j < NB; j++) {          // B: BN*4 chunks / 256 threads
            int q = tid * NB + j;
            int blk = q >> 5, off = q & 31;
            int kG = kt * 2 + (blk & 1);
            const __half* src = (kt < KMAIN)
                ? gB0 + (((size_t)(n0b + (blk >> 1)) * pB0 + kG) << 8) + off * 8
                : gB1 + (((size_t)(n0b + (blk >> 1)) * pB1 + (kG - KMAIN * 2)) << 8) + off * 8;
            CP_ASYNC16(st + A_BYTES + blk * 512 + off * 16, src);
        }
    };

    #pragma unroll
    for (int s = 0; s < STAGES - 1; s++) { load_stage(s, s); CP_COMMIT(); }

    for (int kt = 0; kt < KTOT; kt++) {
        CP_WAIT(STAGES - 2);
        __syncthreads();
        if (kt + STAGES - 1 < KTOT) load_stage(kt + STAGES - 1, (kt + STAGES - 1) % STAGES);
        CP_COMMIT();

        const char* As = smc + (kt % STAGES) * STG;
        const char* Bs = As + A_BYTES;

        #pragma unroll
        for (int ks = 0; ks < 2; ks++) {
            uint4 af[4], bf[NB];
            #pragma unroll
            for (int mi = 0; mi < 4; mi++)
                af[mi] = *reinterpret_cast<const uint4*>(As + ((wm * 4 + mi) * 2 + ks) * 512 + lane * 16);
            #pragma unroll
            for (int nb = 0; nb < NB; nb++)
                bf[nb] = *reinterpret_cast<const uint4*>(Bs + ((wn * NB + nb) * 2 + ks) * 512 + lane * 16);
            #pragma unroll
            for (int mi = 0; mi < 4; mi++)
                #pragma unroll
                for (int nb = 0; nb < NB; nb++) {
                    mma_f16(acc[mi][2 * nb],     af[mi], bf[nb].x, bf[nb].y);
                    mma_f16(acc[mi][2 * nb + 1], af[mi], bf[nb].z, bf[nb].w);
                }
        }
    }

    // ---- epilogue ----
    if constexpr (EPI == 0) {
        float* out = (float*)outv;
        #pragma unroll
        for (int mi = 0; mi < 4; mi++) {
            int row = (m0b + wm * 4 + mi) * 16 + g;
            #pragma unroll
            for (int ni = 0; ni < NI; ni++) {
                int col = n0b * 16 + wn * (BN / 4) + ni * 8 + 2 * c;
                float2 bv = *reinterpret_cast<const float2*>(bias + col);
                float2 o0, o1;
                o0.x = acc[mi][ni][0] + bv.x; o0.y = acc[mi][ni][1] + bv.y;
                o1.x = acc[mi][ni][2] + bv.x; o1.y = acc[mi][ni][3] + bv.y;
                *reinterpret_cast<float2*>(out + (size_t)row * DOUT + col) = o0;
                *reinterpret_cast<float2*>(out + (size_t)(row + 8) * DOUT + col) = o1;
            }
        }
    } else {
        __half* out = (__half*)outv;   // g_uh, A-frag-linear, K=KEXT
        #pragma unroll
        for (int mi = 0; mi < 4; mi++) {
            int mb = m0b + wm * 4 + mi;
            int row = mb * 16 + g;
            int li0 = lidx[row];
            int li1 = lidx[row + 8];
            #pragma unroll
            for (int ni = 0; ni < NI; ni++) {
                int col = wn * (BN / 4) + ni * 8 + 2 * c;   // n0 == 0 for prep
                int kb = col >> 4;                           // == adapter group
                int hk = ni & 1;
                float s0 = (kb == li0) ? 2.0f : 0.0f;
                float s1 = (kb == li1) ? 2.0f : 0.0f;
                size_t off = ((size_t)mb * (KEXT / 16) + kb) * 256 + (g * 4 + c) * 8 + hk * 4;
                *reinterpret_cast<__half2*>(out + off) =
                    __floats2half2_rn(acc[mi][ni][0] * s0, acc[mi][ni][1] * s0);
                *reinterpret_cast<__half2*>(out + off + 2) =
                    __floats2half2_rn(acc[mi][ni][2] * s1, acc[mi][ni][3] * s1);
            }
        }
    }
}

// ============================================================================
// Host side
// ============================================================================
extern "C" void kernel_launch(void* const* d_in, const int* in_sizes, int n_in,
                              void* d_out, int out_size) {
    (void)in_sizes; (void)n_in; (void)out_size;
    const float* x     = (const float*)d_in[0];   // [32768, 2048]
    const float* W     = (const float*)d_in[1];   // [2048, 2048]
    const float* b     = (const float*)d_in[2];   // [2048]
    const float* A_all = (const float*)d_in[3];   // [8, 16, 2048] == A_cat [128, 2048]
    const float* B_all = (const float*)d_in[4];   // [8, 2048, 16]
    const int*   lidx  = (const int*)d_in[5];     // [32768]
    float* out = (float*)d_out;                    // [32768, 2048]

    void *xp, *wp, *ap, *cp, *up;
    cudaGetSymbolAddress(&xp, g_xh);
    cudaGetSymbolAddress(&wp, g_wh);
    cudaGetSymbolAddress(&ap, g_ah);
    cudaGetSymbolAddress(&cp, g_bch);
    cudaGetSymbolAddress(&up, g_uh);
    __half* xh = (__half*)xp;
    __half* wh = (__half*)wp;
    __half* ah = (__half*)ap;
    __half* bch = (__half*)cp;
    __half* uh = (__half*)up;

    // 1) convert operands to fp16 fragment-linear (dest-linear, coalesced)
    {
        int nt = (N_TOK / 16) * (DIN / 16) * 32;
        conv_a_lin<DIN><<<(nt + 255) / 256, 256>>>(x, xh, nt);
    }
    {
        int nt = (DOUT / 16) * (DIN / 16) * 32;
        conv_b_lin<DIN><<<(nt + 255) / 256, 256>>>(W, wh, nt);
    }
    {
        int nt = (KEXT / 16) * (DIN / 16) * 32;
        conv_b_lin<DIN><<<(nt + 255) / 256, 256>>>(A_all, ah, nt);
    }
    {
        int nt = (DOUT / 16) * (KEXT / 16) * 32;
        conv_bcat_lin<<<(nt + 255) / 256, 256>>>(B_all, bch, nt);
    }

    // 2) prep GEMM: g_uh = Afrag( mask(x @ A_cat^T) * 2 )   (BN=128, K=2048)
    {
        constexpr int SMEM = STAGES * (16 * 512 + (128 / 16) * 2 * 512);  // 65536
        cudaFuncSetAttribute((const void*)gemm_f16_kernel<128, DIN / 32, DIN / 32, 1>,
                             cudaFuncAttributeMaxDynamicSharedMemorySize, SMEM);
        gemm_f16_kernel<128, DIN / 32, DIN / 32, 1><<<N_TOK / BM, 256, SMEM>>>(
            xh, xh, DIN / 16, DIN / 16, ah, ah, DIN / 16, DIN / 16, b, lidx, uh, 1);
    }

    // 3) main GEMM: out = [x | u] @ [W | bcat]^T + b   (BN=256, K=2048+128)
    {
        constexpr int SMEM = STAGES * (16 * 512 + (256 / 16) * 2 * 512);  // 98304
        cudaFuncSetAttribute((const void*)gemm_f16_kernel<256, (DIN + KEXT) / 32, DIN / 32, 0>,
                             cudaFuncAttributeMaxDynamicSharedMemorySize, SMEM);
        gemm_f16_kernel<256, (DIN + KEXT) / 32, DIN / 32, 0>
            <<<(N_TOK / BM) * (DOUT / 256), 256, SMEM>>>(
            xh, uh, DIN / 16, KEXT / 16, wh, bch, DIN / 16, KEXT / 16, b, lidx, out, DOUT / 256);
    }
}